// round 1
// baseline (speedup 1.0000x reference)
#include <cuda_runtime.h>
#include <cstdint>

// ---------------------------------------------------------------------------
// TemporalDecoder: 2-layer LSTM (H=256) over BN=1600 folded sequences,
// 64 encoder steps, 10 decoder steps with LayerNorm + 3 MLP heads.
// Recurrent GEMMs use mma.sync m16n8k8 TF32 (fp32 accumulate).
// ---------------------------------------------------------------------------

#define BN_ROWS 1600
#define SEQ     64
#define HDIM    256
#define NSTEPS  10

// ---------------- scratch (static device allocations only) ----------------
__device__ float g_xb [BN_ROWS * SEQ * HDIM];   // x transposed to [BN, S, H]
__device__ float g_h0a[BN_ROWS * HDIM];
__device__ float g_h0b[BN_ROWS * HDIM];
__device__ float g_h1a[BN_ROWS * HDIM];
__device__ float g_h1b[BN_ROWS * HDIM];
__device__ float g_c0 [BN_ROWS * HDIM];
__device__ float g_c1 [BN_ROWS * HDIM];
__device__ float g_ht [BN_ROWS * HDIM];
__device__ float g_hid[BN_ROWS * 512];

// ---------------- small helpers ----------------
__device__ __forceinline__ uint32_t f2tf(float x) {
    uint32_t r;
    asm("cvt.rna.tf32.f32 %0, %1;" : "=r"(r) : "f"(x));
    return r;
}

__device__ __forceinline__ void mma_tf32(float* d, const uint32_t* a,
                                         uint32_t b0, uint32_t b1) {
    asm volatile(
        "mma.sync.aligned.m16n8k8.row.col.f32.tf32.tf32.f32 "
        "{%0,%1,%2,%3}, {%4,%5,%6,%7}, {%8,%9}, {%0,%1,%2,%3};"
        : "+f"(d[0]), "+f"(d[1]), "+f"(d[2]), "+f"(d[3])
        : "r"(a[0]), "r"(a[1]), "r"(a[2]), "r"(a[3]), "r"(b0), "r"(b1));
}

__device__ __forceinline__ float sigf(float x) {
    return 1.0f / (1.0f + __expf(-x));
}

// ---------------------------------------------------------------------------
// Transpose x [B=16, S=64, N=100, H=256] -> xb [BN=1600, S=64, H=256]
// one float4 per thread
// ---------------------------------------------------------------------------
__global__ void transpose_kernel(const float* __restrict__ x) {
    int id = blockIdx.x * blockDim.x + threadIdx.x;   // over 1600*64*64 float4
    if (id >= BN_ROWS * SEQ * (HDIM / 4)) return;
    int h4 = id & 63;
    int t  = (id >> 6) & 63;
    int m  = id >> 12;
    int b  = m / 100;
    int n  = m - b * 100;
    const float4* src = (const float4*)x + (((b * SEQ + t) * 100 + n) * 64 + h4);
    ((float4*)g_xb)[(m * SEQ + t) * 64 + h4] = *src;
}

// zero all state buffers (re-run every replay for determinism)
__global__ void zero_state_kernel() {
    int id = blockIdx.x * blockDim.x + threadIdx.x;
    if (id < BN_ROWS * HDIM) {
        g_h0a[id] = 0.f; g_h0b[id] = 0.f;
        g_h1a[id] = 0.f; g_h1b[id] = 0.f;
        g_c0[id]  = 0.f; g_c1[id]  = 0.f;
    }
}

// ---------------------------------------------------------------------------
// Fused LSTM cell:
//   gates[m][n] = A1[m]·Wih[n] + Hin[m]·Whh[n] + bih[n] + bhh[n]   (n in 0..1023)
//   i,f,g,o = gate slices; Cout = sig(f)*Cin + sig(i)*tanh(g); Hout = sig(o)*tanh(Cout)
// Tile: BM=64 rows x BJ=64 gate-columns (=> 64x256 gate tile, gates interleaved
// in smem B rows: row r -> weight row (r&3)*256 + j0 + (r>>2)).
// 256 threads = 8 warps (2 x m, 4 x n), warp tile 32x64, mma m16n8k8 tf32.
// ---------------------------------------------------------------------------
#define CELL_SMEM_U32 (2*64*20 + 2*256*20 + 256)
#define CELL_SMEM_BYTES (CELL_SMEM_U32 * 4)

__device__ __forceinline__ void cell_fetch(
    int it, const float* __restrict__ A1, int lda1,
    const float* __restrict__ Hin,
    const float* __restrict__ Wih, const float* __restrict__ Whh,
    int m0, int j0, int ar, int c4, float4& ra, float4* rbv)
{
    int kk = it * 16;
    const float* Ap; int lda; const float* Wp;
    if (kk < 256) { Ap = A1;  lda = lda1; Wp = Wih; }
    else          { Ap = Hin; lda = 256;  Wp = Whh; kk -= 256; }
    ra = *(const float4*)(Ap + (m0 + ar) * lda + kk + c4 * 4);
#pragma unroll
    for (int p = 0; p < 4; ++p) {
        int r = ar + 64 * p;
        int wrow = (r & 3) * 256 + j0 + (r >> 2);
        rbv[p] = *(const float4*)(Wp + wrow * 256 + kk + c4 * 4);
    }
}

__device__ __forceinline__ void cell_store(
    uint32_t (*As)[20], uint32_t (*Bs)[20],
    int ar, int c4, const float4& ra, const float4* rbv)
{
    As[ar][c4 * 4 + 0] = f2tf(ra.x);
    As[ar][c4 * 4 + 1] = f2tf(ra.y);
    As[ar][c4 * 4 + 2] = f2tf(ra.z);
    As[ar][c4 * 4 + 3] = f2tf(ra.w);
#pragma unroll
    for (int p = 0; p < 4; ++p) {
        int r = ar + 64 * p;
        Bs[r][c4 * 4 + 0] = f2tf(rbv[p].x);
        Bs[r][c4 * 4 + 1] = f2tf(rbv[p].y);
        Bs[r][c4 * 4 + 2] = f2tf(rbv[p].z);
        Bs[r][c4 * 4 + 3] = f2tf(rbv[p].w);
    }
}

__global__ void __launch_bounds__(256, 1)
lstm_cell_kernel(const float* __restrict__ A1, int lda1,
                 const float* __restrict__ Wih,
                 const float* __restrict__ Hin,
                 const float* __restrict__ Whh,
                 const float* __restrict__ bih,
                 const float* __restrict__ bhh,
                 const float* __restrict__ Cin,
                 float* __restrict__ Cout,
                 float* __restrict__ Hout)
{
    extern __shared__ uint32_t smbuf[];
    uint32_t (*As0)[20] = (uint32_t(*)[20])(smbuf);
    uint32_t (*As1)[20] = (uint32_t(*)[20])(smbuf + 64 * 20);
    uint32_t (*Bs0)[20] = (uint32_t(*)[20])(smbuf + 2 * 64 * 20);
    uint32_t (*Bs1)[20] = (uint32_t(*)[20])(smbuf + 2 * 64 * 20 + 256 * 20);
    float*    biasS     = (float*)(smbuf + 2 * 64 * 20 + 2 * 256 * 20);

    const int m0  = blockIdx.x * 64;
    const int j0  = blockIdx.y * 64;
    const int tid = threadIdx.x;
    const int lane = tid & 31;
    const int wid  = tid >> 5;
    const int wm   = wid >> 2;     // 0..1
    const int wn   = wid & 3;      // 0..3
    const int g4   = lane >> 2;    // 0..7
    const int t4   = lane & 3;     // 0..3

    {   // combined bias tile, layout [gate*64 + jj]
        int gate = tid >> 6, jj = tid & 63;
        int gn = gate * 256 + j0 + jj;
        biasS[tid] = bih[gn] + bhh[gn];
    }

    float acc[2][8][4];
#pragma unroll
    for (int i = 0; i < 2; ++i)
#pragma unroll
        for (int j = 0; j < 8; ++j)
#pragma unroll
            for (int k = 0; k < 4; ++k) acc[i][j][k] = 0.f;

    const int ar = tid >> 2;   // 0..63
    const int c4 = tid & 3;    // 0..3

    float4 ra; float4 rbv[4];
    cell_fetch(0, A1, lda1, Hin, Wih, Whh, m0, j0, ar, c4, ra, rbv);
    cell_store(As0, Bs0, ar, c4, ra, rbv);
    __syncthreads();

    for (int it = 0; it < 32; ++it) {
        uint32_t (*Acur)[20] = (it & 1) ? As1 : As0;
        uint32_t (*Bcur)[20] = (it & 1) ? Bs1 : Bs0;
        bool more = (it + 1) < 32;
        if (more)
            cell_fetch(it + 1, A1, lda1, Hin, Wih, Whh, m0, j0, ar, c4, ra, rbv);

#pragma unroll
        for (int ks = 0; ks < 16; ks += 8) {
            uint32_t af[2][4];
#pragma unroll
            for (int mf = 0; mf < 2; ++mf) {
                int r = wm * 32 + mf * 16 + g4;
                af[mf][0] = Acur[r    ][ks + t4];
                af[mf][1] = Acur[r + 8][ks + t4];
                af[mf][2] = Acur[r    ][ks + t4 + 4];
                af[mf][3] = Acur[r + 8][ks + t4 + 4];
            }
#pragma unroll
            for (int nf = 0; nf < 8; ++nf) {
                int rbrow = wn * 64 + nf * 8 + g4;
                uint32_t b0 = Bcur[rbrow][ks + t4];
                uint32_t b1 = Bcur[rbrow][ks + t4 + 4];
                mma_tf32(acc[0][nf], af[0], b0, b1);
                mma_tf32(acc[1][nf], af[1], b0, b1);
            }
        }
        if (more) {
            uint32_t (*Anx)[20] = (it & 1) ? As0 : As1;
            uint32_t (*Bnx)[20] = (it & 1) ? Bs0 : Bs1;
            cell_store(Anx, Bnx, ar, c4, ra, rbv);
        }
        __syncthreads();
    }

    // ------------- epilogue: gather 4 gates per (row, j), apply LSTM -------------
    // column of acc[..][nf][0] = wn*64 + nf*8 + 2*t4 ; gate = col & 3 ; j = col >> 2
    const bool oddl = (t4 & 1);
    const unsigned FULL = 0xffffffffu;
#pragma unroll
    for (int mf = 0; mf < 2; ++mf) {
#pragma unroll
        for (int nf = 0; nf < 8; ++nf) {
            float c0 = acc[mf][nf][0], c1 = acc[mf][nf][1];
            float c2 = acc[mf][nf][2], c3 = acc[mf][nf][3];
            float x0 = __shfl_xor_sync(FULL, c0, 1);
            float x1 = __shfl_xor_sync(FULL, c1, 1);
            float x2 = __shfl_xor_sync(FULL, c2, 1);
            float x3 = __shfl_xor_sync(FULL, c3, 1);
            float gi, gf, gg, go; int rloc;
            if (!oddl) { gi = c0; gf = c1; gg = x0; go = x1; rloc = g4; }
            else       { gi = x2; gf = x3; gg = c2; go = c3; rloc = g4 + 8; }
            int jj    = wn * 16 + nf * 2 + (t4 >> 1);
            int rglob = m0 + wm * 32 + mf * 16 + rloc;
            int jglob = j0 + jj;
            gi += biasS[jj];
            gf += biasS[64 + jj];
            gg += biasS[128 + jj];
            go += biasS[192 + jj];
            float cold = Cin[rglob * 256 + jglob];
            float cn = sigf(gf) * cold + sigf(gi) * tanhf(gg);
            float hn = sigf(go) * tanhf(cn);
            Cout[rglob * 256 + jglob] = cn;
            Hout[rglob * 256 + jglob] = hn;
        }
    }
}

// ---------------------------------------------------------------------------
// heads layer-1: hid[1600,512] = relu(ht @ [cen_w1;svd_w1;lsvd_w1]^T + b)
// BM=64 x BN=64, K=256, tf32 mma. warp tile 32x16.
// ---------------------------------------------------------------------------
__global__ void __launch_bounds__(256, 1)
heads1_kernel(const float* __restrict__ ht,
              const float* __restrict__ cw1, const float* __restrict__ cb1,
              const float* __restrict__ sw1, const float* __restrict__ sb1,
              const float* __restrict__ lw1, const float* __restrict__ lb1,
              float* __restrict__ hid)
{
    __shared__ uint32_t As[2][64][20];
    __shared__ uint32_t Bs[2][64][20];
    __shared__ float biasS[64];

    const int m0  = blockIdx.x * 64;
    const int n0  = blockIdx.y * 64;
    const int tid = threadIdx.x;
    const int lane = tid & 31;
    const int wid  = tid >> 5;
    const int wm   = wid >> 2;
    const int wn   = wid & 3;
    const int g4   = lane >> 2;
    const int t4   = lane & 3;

    if (tid < 64) {
        int n = n0 + tid; float bv;
        if (n < 128) bv = cb1[n];
        else if (n < 256) bv = sb1[n - 128];
        else bv = lb1[n - 256];
        biasS[tid] = bv;
    }

    float acc[2][2][4];
#pragma unroll
    for (int i = 0; i < 2; ++i)
#pragma unroll
        for (int j = 0; j < 2; ++j)
#pragma unroll
            for (int k = 0; k < 4; ++k) acc[i][j][k] = 0.f;

    const int ar = tid >> 2;
    const int c4 = tid & 3;

    // B row -> weight pointer (fixed per thread across iters)
    const float* wp; int wr;
    {
        int n = n0 + ar;
        if (n < 128)      { wp = cw1; wr = n; }
        else if (n < 256) { wp = sw1; wr = n - 128; }
        else              { wp = lw1; wr = n - 256; }
    }

    float4 ra, rb;
    // prefetch iter 0
    ra = *(const float4*)(ht + (m0 + ar) * 256 + c4 * 4);
    rb = *(const float4*)(wp + wr * 256 + c4 * 4);
    {
        As[0][ar][c4*4+0]=f2tf(ra.x); As[0][ar][c4*4+1]=f2tf(ra.y);
        As[0][ar][c4*4+2]=f2tf(ra.z); As[0][ar][c4*4+3]=f2tf(ra.w);
        Bs[0][ar][c4*4+0]=f2tf(rb.x); Bs[0][ar][c4*4+1]=f2tf(rb.y);
        Bs[0][ar][c4*4+2]=f2tf(rb.z); Bs[0][ar][c4*4+3]=f2tf(rb.w);
    }
    __syncthreads();

    for (int it = 0; it < 16; ++it) {
        int buf = it & 1;
        bool more = (it + 1) < 16;
        if (more) {
            int kk = (it + 1) * 16;
            ra = *(const float4*)(ht + (m0 + ar) * 256 + kk + c4 * 4);
            rb = *(const float4*)(wp + wr * 256 + kk + c4 * 4);
        }
#pragma unroll
        for (int ks = 0; ks < 16; ks += 8) {
            uint32_t af[2][4];
#pragma unroll
            for (int mf = 0; mf < 2; ++mf) {
                int r = wm * 32 + mf * 16 + g4;
                af[mf][0] = As[buf][r    ][ks + t4];
                af[mf][1] = As[buf][r + 8][ks + t4];
                af[mf][2] = As[buf][r    ][ks + t4 + 4];
                af[mf][3] = As[buf][r + 8][ks + t4 + 4];
            }
#pragma unroll
            for (int nf = 0; nf < 2; ++nf) {
                int rbrow = wn * 16 + nf * 8 + g4;
                uint32_t b0 = Bs[buf][rbrow][ks + t4];
                uint32_t b1 = Bs[buf][rbrow][ks + t4 + 4];
                mma_tf32(acc[0][nf], af[0], b0, b1);
                mma_tf32(acc[1][nf], af[1], b0, b1);
            }
        }
        if (more) {
            int nb = (it + 1) & 1;
            As[nb][ar][c4*4+0]=f2tf(ra.x); As[nb][ar][c4*4+1]=f2tf(ra.y);
            As[nb][ar][c4*4+2]=f2tf(ra.z); As[nb][ar][c4*4+3]=f2tf(ra.w);
            Bs[nb][ar][c4*4+0]=f2tf(rb.x); Bs[nb][ar][c4*4+1]=f2tf(rb.y);
            Bs[nb][ar][c4*4+2]=f2tf(rb.z); Bs[nb][ar][c4*4+3]=f2tf(rb.w);
        }
        __syncthreads();
    }

#pragma unroll
    for (int mf = 0; mf < 2; ++mf) {
#pragma unroll
        for (int nf = 0; nf < 2; ++nf) {
            int col = wn * 16 + nf * 8 + 2 * t4;
            int row = m0 + wm * 32 + mf * 16 + g4;
            int n   = n0 + col;
            float v0 = acc[mf][nf][0] + biasS[col];
            float v1 = acc[mf][nf][1] + biasS[col + 1];
            float v2 = acc[mf][nf][2] + biasS[col];
            float v3 = acc[mf][nf][3] + biasS[col + 1];
            hid[row * 512 + n]           = fmaxf(v0, 0.f);
            hid[row * 512 + n + 1]       = fmaxf(v1, 0.f);
            hid[(row + 8) * 512 + n]     = fmaxf(v2, 0.f);
            hid[(row + 8) * 512 + n + 1] = fmaxf(v3, 0.f);
        }
    }
}

// ---------------------------------------------------------------------------
// heads layer-2: 22 tiny dot products per row, written straight to d_out
// out[b, s, n, k], m = b*100 + n
// ---------------------------------------------------------------------------
__global__ void __launch_bounds__(128)
heads2_kernel(const float* __restrict__ hid,
              const float* __restrict__ cw2, const float* __restrict__ cb2,
              const float* __restrict__ sw2, const float* __restrict__ sb2,
              const float* __restrict__ lw2, const float* __restrict__ lb2,
              float* __restrict__ out, int s)
{
    int m = blockIdx.x;
    __shared__ float hs[512];
    for (int i = threadIdx.x; i < 512; i += 128) hs[i] = hid[m * 512 + i];
    __syncthreads();

    int wid = threadIdx.x >> 5, lane = threadIdx.x & 31;
    int b = m / 100, n = m - b * 100;
    float* obase = out + (((b * NSTEPS + s) * 100 + n) * 22);

    for (int o = wid; o < 22; o += 4) {
        const float* w; float bb; int base, klen;
        if (o < 4)       { w = cw2 + o * 128;        bb = cb2[o];     base = 0;   klen = 128; }
        else if (o < 6)  { w = sw2 + (o - 4) * 128;  bb = sb2[o - 4]; base = 128; klen = 128; }
        else             { w = lw2 + (o - 6) * 256;  bb = lb2[o - 6]; base = 256; klen = 256; }
        float acc = 0.f;
        for (int k = lane; k < klen; k += 32) acc += hs[base + k] * w[k];
#pragma unroll
        for (int off = 16; off; off >>= 1) acc += __shfl_xor_sync(0xffffffffu, acc, off);
        if (lane == 0) obase[o] = acc + bb;
    }
}

// ---------------------------------------------------------------------------
// LayerNorm over last dim (256), one block per row
// ---------------------------------------------------------------------------
__global__ void __launch_bounds__(256)
ln_kernel(const float* __restrict__ hin, const float* __restrict__ gamma,
          const float* __restrict__ beta, float* __restrict__ outp)
{
    int m = blockIdx.x, t = threadIdx.x;
    float v = hin[m * 256 + t];
    float s1 = v, s2 = v * v;
#pragma unroll
    for (int o = 16; o; o >>= 1) {
        s1 += __shfl_xor_sync(0xffffffffu, s1, o);
        s2 += __shfl_xor_sync(0xffffffffu, s2, o);
    }
    __shared__ float r1[8], r2[8];
    if ((t & 31) == 0) { r1[t >> 5] = s1; r2[t >> 5] = s2; }
    __syncthreads();
    float S1 = 0.f, S2 = 0.f;
#pragma unroll
    for (int i = 0; i < 8; ++i) { S1 += r1[i]; S2 += r2[i]; }
    float mean = S1 * (1.f / 256.f);
    float var  = S2 * (1.f / 256.f) - mean * mean;
    outp[m * 256 + t] = (v - mean) * rsqrtf(var + 1e-5f) * gamma[t] + beta[t];
}

// ---------------------------------------------------------------------------
extern "C" void kernel_launch(void* const* d_in, const int* in_sizes, int n_in,
                              void* d_out, int out_size)
{
    (void)in_sizes; (void)n_in; (void)out_size;
    const float* x    = (const float*)d_in[0];
    const float* Wih0 = (const float*)d_in[1];
    const float* Whh0 = (const float*)d_in[2];
    const float* bih0 = (const float*)d_in[3];
    const float* bhh0 = (const float*)d_in[4];
    const float* Wih1 = (const float*)d_in[5];
    const float* Whh1 = (const float*)d_in[6];
    const float* bih1 = (const float*)d_in[7];
    const float* bhh1 = (const float*)d_in[8];
    const float* lng  = (const float*)d_in[9];
    const float* lnb  = (const float*)d_in[10];
    const float* cw1  = (const float*)d_in[11];
    const float* cb1  = (const float*)d_in[12];
    const float* cw2  = (const float*)d_in[13];
    const float* cb2  = (const float*)d_in[14];
    const float* sw1  = (const float*)d_in[15];
    const float* sb1  = (const float*)d_in[16];
    const float* sw2  = (const float*)d_in[17];
    const float* sb2  = (const float*)d_in[18];
    const float* lw1  = (const float*)d_in[19];
    const float* lb1  = (const float*)d_in[20];
    const float* lw2  = (const float*)d_in[21];
    const float* lb2  = (const float*)d_in[22];
    float* out = (float*)d_out;

    float *xb, *h0a, *h0b, *h1a, *h1b, *c0, *c1, *ht, *hid;
    cudaGetSymbolAddress((void**)&xb,  g_xb);
    cudaGetSymbolAddress((void**)&h0a, g_h0a);
    cudaGetSymbolAddress((void**)&h0b, g_h0b);
    cudaGetSymbolAddress((void**)&h1a, g_h1a);
    cudaGetSymbolAddress((void**)&h1b, g_h1b);
    cudaGetSymbolAddress((void**)&c0,  g_c0);
    cudaGetSymbolAddress((void**)&c1,  g_c1);
    cudaGetSymbolAddress((void**)&ht,  g_ht);
    cudaGetSymbolAddress((void**)&hid, g_hid);

    cudaFuncSetAttribute(lstm_cell_kernel,
                         cudaFuncAttributeMaxDynamicSharedMemorySize,
                         CELL_SMEM_BYTES);

    float* H0[2] = {h0a, h0b};
    float* H1[2] = {h1a, h1b};

    transpose_kernel<<<25600, 256>>>(x);
    zero_state_kernel<<<1600, 256>>>();

    dim3 cgrid(25, 4);
    int p0 = 0, p1 = 0;
    for (int t = 0; t < SEQ; ++t) {
        lstm_cell_kernel<<<cgrid, 256, CELL_SMEM_BYTES>>>(
            xb + t * 256, SEQ * 256, Wih0, H0[p0], Whh0, bih0, bhh0,
            c0, c0, H0[p0 ^ 1]);
        lstm_cell_kernel<<<cgrid, 256, CELL_SMEM_BYTES>>>(
            H0[p0 ^ 1], 256, Wih1, H1[p1], Whh1, bih1, bhh1,
            c1, c1, H1[p1 ^ 1]);
        p0 ^= 1; p1 ^= 1;
    }
    ln_kernel<<<1600, 256>>>(H1[p1], lng, lnb, ht);

    for (int s = 0; s < NSTEPS; ++s) {
        heads1_kernel<<<dim3(25, 8), 256>>>(ht, cw1, cb1, sw1, sb1, lw1, lb1, hid);
        heads2_kernel<<<1600, 128>>>(hid, cw2, cb2, sw2, sb2, lw2, lb2, out, s);
        if (s < NSTEPS - 1) {
            lstm_cell_kernel<<<cgrid, 256, CELL_SMEM_BYTES>>>(
                ht, 256, Wih0, H0[p0], Whh0, bih0, bhh0, c0, c0, H0[p0 ^ 1]);
            lstm_cell_kernel<<<cgrid, 256, CELL_SMEM_BYTES>>>(
                H0[p0 ^ 1], 256, Wih1, H1[p1], Whh1, bih1, bhh1, c1, c1, H1[p1 ^ 1]);
            p0 ^= 1; p1 ^= 1;
            ln_kernel<<<1600, 256>>>(H1[p1 ^ 0], lng, lnb, ht);
        }
    }
}

// round 2
// speedup vs baseline: 4.3792x; 4.3792x over previous
#include <cuda_runtime.h>
#include <cstdint>

#define BNR   1600
#define HD    256
#define SEQ   64
#define NSTEPS 10

// ------------------------- static device scratch --------------------------
__device__ uint32_t g_xbt[BNR * SEQ * HD];      // x as tf32, [m][t][k]
__device__ uint32_t g_h0tf[2][BNR * HD];
__device__ uint32_t g_h1tf[2][BNR * HD];
__device__ uint32_t g_httf[BNR * HD];
__device__ float    g_h1f [BNR * HD];
__device__ float    g_c0  [BNR * HD];
__device__ float    g_c1  [BNR * HD];
__device__ float    g_hid [BNR * 512];
__device__ uint32_t g_Wre0[1024 * 512];         // tf32, rows (j*4+g), k = [Wih|Whh]
__device__ uint32_t g_Wre1[1024 * 512];
__device__ float    g_bre0[1024];
__device__ float    g_bre1[1024];
__device__ uint32_t g_Wh1 [512 * 256];          // heads layer1 weights tf32
__device__ float    g_bh1 [512];

// ------------------------------ helpers -----------------------------------
__device__ __forceinline__ uint32_t f2tf(float x) {
    uint32_t r;
    asm("cvt.rna.tf32.f32 %0, %1;" : "=r"(r) : "f"(x));
    return r;
}

__device__ __forceinline__ void mma_tf32(float* d, const uint32_t* a,
                                         uint32_t b0, uint32_t b1) {
    asm volatile(
        "mma.sync.aligned.m16n8k8.row.col.f32.tf32.tf32.f32 "
        "{%0,%1,%2,%3}, {%4,%5,%6,%7}, {%8,%9}, {%0,%1,%2,%3};"
        : "+f"(d[0]), "+f"(d[1]), "+f"(d[2]), "+f"(d[3])
        : "r"(a[0]), "r"(a[1]), "r"(a[2]), "r"(a[3]), "r"(b0), "r"(b1));
}

__device__ __forceinline__ float sigf(float x) {
    return 1.0f / (1.0f + __expf(-x));
}

__device__ __forceinline__ void cpa16(uint32_t saddr, const void* g, int sz) {
    asm volatile("cp.async.cg.shared.global [%0], [%1], 16, %2;"
                 :: "r"(saddr), "l"(g), "r"(sz));
}
#define CP_COMMIT() asm volatile("cp.async.commit_group;")
#define CP_WAIT1()  asm volatile("cp.async.wait_group 1;")
#define CP_WAIT0()  asm volatile("cp.async.wait_group 0;")

// ------------------------------ setup kernels -----------------------------
// x [16,64,100,256] -> g_xbt [m=1600][t=64][k=256] tf32
__global__ void transpose_kernel(const float* __restrict__ x) {
    int id = blockIdx.x * blockDim.x + threadIdx.x;     // 1600*64*64 float4
    if (id >= BNR * SEQ * (HD / 4)) return;
    int h4 = id & 63;
    int t  = (id >> 6) & 63;
    int m  = id >> 12;
    int b  = m / 100;
    int n  = m - b * 100;
    float4 v = ((const float4*)x)[(((b * SEQ + t) * 100 + n) * 64 + h4)];
    uint4 o;
    o.x = f2tf(v.x); o.y = f2tf(v.y); o.z = f2tf(v.z); o.w = f2tf(v.w);
    ((uint4*)g_xbt)[(m * SEQ + t) * 64 + h4] = o;
}

__global__ void rearr_w_kernel(const float* __restrict__ Wih,
                               const float* __restrict__ Whh,
                               const float* __restrict__ bih,
                               const float* __restrict__ bhh,
                               uint32_t* __restrict__ Wre,
                               float* __restrict__ bre) {
    int id = blockIdx.x * 256 + threadIdx.x;   // 1024*512
    int nre = id >> 9, k = id & 511;
    int j = nre >> 2, g = nre & 3;
    int srow = g * 256 + j;
    float v = (k < 256) ? Wih[srow * 256 + k] : Whh[srow * 256 + k - 256];
    Wre[id] = f2tf(v);
    if (k == 0) bre[nre] = bih[srow] + bhh[srow];
}

__global__ void rearr_h1_kernel(const float* __restrict__ cw1, const float* __restrict__ cb1,
                                const float* __restrict__ sw1, const float* __restrict__ sb1,
                                const float* __restrict__ lw1, const float* __restrict__ lb1) {
    int id = blockIdx.x * 256 + threadIdx.x;   // 512*256
    int row = id >> 8, k = id & 255;
    float v, b;
    if (row < 128)      { v = cw1[row * 256 + k];         b = cb1[row]; }
    else if (row < 256) { v = sw1[(row - 128) * 256 + k]; b = sb1[row - 128]; }
    else                { v = lw1[(row - 256) * 256 + k]; b = lb1[row - 256]; }
    g_Wh1[id] = f2tf(v);
    if (k == 0) g_bh1[row] = b;
}

__global__ void zero_state_kernel() {
    int id = blockIdx.x * blockDim.x + threadIdx.x;
    if (id < BNR * HD) {
        g_c0[id] = 0.f; g_c1[id] = 0.f;
        g_h0tf[0][id] = 0u; g_h0tf[1][id] = 0u;
        g_h1tf[0][id] = 0u; g_h1tf[1][id] = 0u;
    }
}

// ---------------------------------------------------------------------------
// LSTM cell GEMM: gates[1600][1024re] = A0@W[:, :256]^T-ish + A1@W[:,256:]^T
//   A0, A1: tf32 [1600][256] (lda in u32 elems), W: tf32 [1024][512] rearranged
//   BM=128, 8 j-cols (32 weight rows) per CTA, K=512 in 16 chunks of 32.
//   2-stage cp.async pipeline. Epilogue = LSTM activations.
// ---------------------------------------------------------------------------
__global__ void __launch_bounds__(256, 2)
cell_kernel(const uint32_t* __restrict__ A0, int lda0,
            const uint32_t* __restrict__ A1, int lda1,
            const uint32_t* __restrict__ W,
            const float* __restrict__ bre,
            float* __restrict__ Cio,
            float* __restrict__ Hf32,
            uint32_t* __restrict__ Htf)
{
    __shared__ __align__(16) uint32_t As[2][128][36];
    __shared__ __align__(16) uint32_t Bs[2][32][36];
    __shared__ float biasS[32];

    const int tid = threadIdx.x;
    const int m0 = blockIdx.x * 128;
    const int j0 = blockIdx.y * 8;

    if (tid < 32) biasS[tid] = bre[j0 * 4 + tid];

    const int arow = tid >> 3;         // 0..31
    const int ac4  = tid & 7;          // 0..7

    uint32_t sA[4], sB;
#pragma unroll
    for (int q = 0; q < 4; ++q)
        sA[q] = (uint32_t)__cvta_generic_to_shared(&As[0][arow + 32 * q][ac4 * 4]);
    sB = (uint32_t)__cvta_generic_to_shared(&Bs[0][arow][ac4 * 4]);
    const uint32_t stA = 128 * 36 * 4;
    const uint32_t stB = 32 * 36 * 4;

    int mrow[4]; int msz[4];
#pragma unroll
    for (int q = 0; q < 4; ++q) {
        int m = m0 + arow + 32 * q;
        bool p = m < BNR;
        mrow[q] = p ? m : 0;
        msz[q]  = p ? 16 : 0;
    }

    const uint32_t* bbase = W + (j0 * 4 + arow) * 512 + ac4 * 4;

    const int lane = tid & 31, wid = tid >> 5;
    const int wm = wid >> 1, wn = wid & 1;     // 4 warps M x 2 warps N
    const int g4 = lane >> 2, t4 = lane & 3;

    float acc[2][2][4];
#pragma unroll
    for (int a = 0; a < 2; ++a)
#pragma unroll
        for (int b = 0; b < 2; ++b)
#pragma unroll
            for (int k = 0; k < 4; ++k) acc[a][b][k] = 0.f;

#define ISSUE(c, st)                                                          \
    do {                                                                      \
        const uint32_t* ab; int lda, kk;                                      \
        if ((c) < 8) { ab = A0; lda = lda0; kk = (c) * 32; }                  \
        else         { ab = A1; lda = lda1; kk = ((c) - 8) * 32; }            \
        _Pragma("unroll")                                                     \
        for (int q = 0; q < 4; ++q)                                           \
            cpa16(sA[q] + (st) * stA, ab + (long)mrow[q] * lda + kk + ac4 * 4,\
                  msz[q]);                                                    \
        cpa16(sB + (st) * stB, bbase + (c) * 32, 16);                         \
        CP_COMMIT();                                                          \
    } while (0)

    ISSUE(0, 0);
    ISSUE(1, 1);

    for (int c = 0; c < 16; ++c) {
        const int st = c & 1;
        if (c < 15) CP_WAIT1(); else CP_WAIT0();
        __syncthreads();
#pragma unroll
        for (int ks = 0; ks < 32; ks += 8) {
            uint32_t af[2][4], b0[2], b1[2];
#pragma unroll
            for (int mf = 0; mf < 2; ++mf) {
                int r = wm * 32 + mf * 16 + g4;
                af[mf][0] = As[st][r    ][ks + t4];
                af[mf][1] = As[st][r + 8][ks + t4];
                af[mf][2] = As[st][r    ][ks + t4 + 4];
                af[mf][3] = As[st][r + 8][ks + t4 + 4];
            }
#pragma unroll
            for (int nf = 0; nf < 2; ++nf) {
                int rb = wn * 16 + nf * 8 + g4;
                b0[nf] = Bs[st][rb][ks + t4];
                b1[nf] = Bs[st][rb][ks + t4 + 4];
            }
#pragma unroll
            for (int mf = 0; mf < 2; ++mf)
#pragma unroll
                for (int nf = 0; nf < 2; ++nf)
                    mma_tf32(acc[mf][nf], af[mf], b0[nf], b1[nf]);
        }
        __syncthreads();
        if (c + 2 < 16) ISSUE(c + 2, st);
    }
#undef ISSUE

    // ---------------- LSTM epilogue -------------------
    const bool oddl = (t4 & 1);
    const unsigned FULL = 0xffffffffu;
#pragma unroll
    for (int mf = 0; mf < 2; ++mf) {
#pragma unroll
        for (int nf = 0; nf < 2; ++nf) {
            float c0v = acc[mf][nf][0], c1v = acc[mf][nf][1];
            float c2v = acc[mf][nf][2], c3v = acc[mf][nf][3];
            float x0 = __shfl_xor_sync(FULL, c0v, 1);
            float x1 = __shfl_xor_sync(FULL, c1v, 1);
            float x2 = __shfl_xor_sync(FULL, c2v, 1);
            float x3 = __shfl_xor_sync(FULL, c3v, 1);
            float gi, gf, gg, go; int rloc;
            if (!oddl) { gi = c0v; gf = c1v; gg = x0;  go = x1;  rloc = g4; }
            else       { gi = x2;  gf = x3;  gg = c2v; go = c3v; rloc = g4 + 8; }
            int rglob = m0 + wm * 32 + mf * 16 + rloc;
            if (rglob >= BNR) continue;
            int jl = wn * 4 + nf * 2 + (t4 >> 1);
            int jglob = j0 + jl;
            gi += biasS[jl * 4 + 0];
            gf += biasS[jl * 4 + 1];
            gg += biasS[jl * 4 + 2];
            go += biasS[jl * 4 + 3];
            float cold = Cio[rglob * HD + jglob];
            float cn = sigf(gf) * cold + sigf(gi) * tanhf(gg);
            float hn = sigf(go) * tanhf(cn);
            Cio[rglob * HD + jglob] = cn;
            if (Hf32) Hf32[rglob * HD + jglob] = hn;
            Htf[rglob * HD + jglob] = f2tf(hn);
        }
    }
}

// ---------------------------------------------------------------------------
// heads layer-1: hid[1600][512] = relu(httf @ Wh1^T + b). BM=128, 32 n/CTA,
// K=256 (8 chunks). Same pipeline skeleton.
// ---------------------------------------------------------------------------
__global__ void __launch_bounds__(256, 2)
heads1_kernel(const uint32_t* __restrict__ A0,
              const uint32_t* __restrict__ W,
              const float* __restrict__ bias,
              float* __restrict__ hid)
{
    __shared__ __align__(16) uint32_t As[2][128][36];
    __shared__ __align__(16) uint32_t Bs[2][32][36];
    __shared__ float biasS[32];

    const int tid = threadIdx.x;
    const int m0 = blockIdx.x * 128;
    const int n0 = blockIdx.y * 32;

    if (tid < 32) biasS[tid] = bias[n0 + tid];

    const int arow = tid >> 3;
    const int ac4  = tid & 7;

    uint32_t sA[4], sB;
#pragma unroll
    for (int q = 0; q < 4; ++q)
        sA[q] = (uint32_t)__cvta_generic_to_shared(&As[0][arow + 32 * q][ac4 * 4]);
    sB = (uint32_t)__cvta_generic_to_shared(&Bs[0][arow][ac4 * 4]);
    const uint32_t stA = 128 * 36 * 4;
    const uint32_t stB = 32 * 36 * 4;

    int mrow[4]; int msz[4];
#pragma unroll
    for (int q = 0; q < 4; ++q) {
        int m = m0 + arow + 32 * q;
        bool p = m < BNR;
        mrow[q] = p ? m : 0;
        msz[q]  = p ? 16 : 0;
    }
    const uint32_t* bbase = W + (n0 + arow) * 256 + ac4 * 4;

    const int lane = tid & 31, wid = tid >> 5;
    const int wm = wid >> 1, wn = wid & 1;
    const int g4 = lane >> 2, t4 = lane & 3;

    float acc[2][2][4];
#pragma unroll
    for (int a = 0; a < 2; ++a)
#pragma unroll
        for (int b = 0; b < 2; ++b)
#pragma unroll
            for (int k = 0; k < 4; ++k) acc[a][b][k] = 0.f;

#define ISSUE(c, st)                                                          \
    do {                                                                      \
        int kk = (c) * 32;                                                    \
        _Pragma("unroll")                                                     \
        for (int q = 0; q < 4; ++q)                                           \
            cpa16(sA[q] + (st) * stA, A0 + (long)mrow[q] * 256 + kk + ac4 * 4,\
                  msz[q]);                                                    \
        cpa16(sB + (st) * stB, bbase + kk, 16);                               \
        CP_COMMIT();                                                          \
    } while (0)

    ISSUE(0, 0);
    ISSUE(1, 1);

    for (int c = 0; c < 8; ++c) {
        const int st = c & 1;
        if (c < 7) CP_WAIT1(); else CP_WAIT0();
        __syncthreads();
#pragma unroll
        for (int ks = 0; ks < 32; ks += 8) {
            uint32_t af[2][4], b0[2], b1[2];
#pragma unroll
            for (int mf = 0; mf < 2; ++mf) {
                int r = wm * 32 + mf * 16 + g4;
                af[mf][0] = As[st][r    ][ks + t4];
                af[mf][1] = As[st][r + 8][ks + t4];
                af[mf][2] = As[st][r    ][ks + t4 + 4];
                af[mf][3] = As[st][r + 8][ks + t4 + 4];
            }
#pragma unroll
            for (int nf = 0; nf < 2; ++nf) {
                int rb = wn * 16 + nf * 8 + g4;
                b0[nf] = Bs[st][rb][ks + t4];
                b1[nf] = Bs[st][rb][ks + t4 + 4];
            }
#pragma unroll
            for (int mf = 0; mf < 2; ++mf)
#pragma unroll
                for (int nf = 0; nf < 2; ++nf)
                    mma_tf32(acc[mf][nf], af[mf], b0[nf], b1[nf]);
        }
        __syncthreads();
        if (c + 2 < 8) ISSUE(c + 2, st);
    }
#undef ISSUE

#pragma unroll
    for (int mf = 0; mf < 2; ++mf) {
#pragma unroll
        for (int nf = 0; nf < 2; ++nf) {
            int col = wn * 16 + nf * 8 + 2 * t4;
            int r0 = m0 + wm * 32 + mf * 16 + g4;
            float v0 = acc[mf][nf][0] + biasS[col];
            float v1 = acc[mf][nf][1] + biasS[col + 1];
            float v2 = acc[mf][nf][2] + biasS[col];
            float v3 = acc[mf][nf][3] + biasS[col + 1];
            if (r0 < BNR) {
                hid[r0 * 512 + n0 + col]     = fmaxf(v0, 0.f);
                hid[r0 * 512 + n0 + col + 1] = fmaxf(v1, 0.f);
            }
            if (r0 + 8 < BNR) {
                hid[(r0 + 8) * 512 + n0 + col]     = fmaxf(v2, 0.f);
                hid[(r0 + 8) * 512 + n0 + col + 1] = fmaxf(v3, 0.f);
            }
        }
    }
}

// ---------------------------------------------------------------------------
// heads layer-2: 22 tiny dot products, straight to d_out
// ---------------------------------------------------------------------------
__global__ void __launch_bounds__(128)
heads2_kernel(const float* __restrict__ hid,
              const float* __restrict__ cw2, const float* __restrict__ cb2,
              const float* __restrict__ sw2, const float* __restrict__ sb2,
              const float* __restrict__ lw2, const float* __restrict__ lb2,
              float* __restrict__ out, int s)
{
    int m = blockIdx.x;
    __shared__ float hs[512];
    for (int i = threadIdx.x; i < 512; i += 128) hs[i] = hid[m * 512 + i];
    __syncthreads();

    int wid = threadIdx.x >> 5, lane = threadIdx.x & 31;
    int b = m / 100, n = m - b * 100;
    float* obase = out + (((b * NSTEPS + s) * 100 + n) * 22);

    for (int o = wid; o < 22; o += 4) {
        const float* w; float bb; int base, klen;
        if (o < 4)       { w = cw2 + o * 128;        bb = cb2[o];     base = 0;   klen = 128; }
        else if (o < 6)  { w = sw2 + (o - 4) * 128;  bb = sb2[o - 4]; base = 128; klen = 128; }
        else             { w = lw2 + (o - 6) * 256;  bb = lb2[o - 6]; base = 256; klen = 256; }
        float acc = 0.f;
        for (int k = lane; k < klen; k += 32) acc += hs[base + k] * w[k];
#pragma unroll
        for (int off = 16; off; off >>= 1)
            acc += __shfl_xor_sync(0xffffffffu, acc, off);
        if (lane == 0) obase[o] = acc + bb;
    }
}

// ---------------------------------------------------------------------------
// LayerNorm over H=256, writes tf32 output for downstream GEMMs
// ---------------------------------------------------------------------------
__global__ void __launch_bounds__(256)
ln_kernel(const float* __restrict__ hin, const float* __restrict__ gamma,
          const float* __restrict__ beta, uint32_t* __restrict__ outtf)
{
    int m = blockIdx.x, t = threadIdx.x;
    float v = hin[m * 256 + t];
    float s1 = v, s2 = v * v;
#pragma unroll
    for (int o = 16; o; o >>= 1) {
        s1 += __shfl_xor_sync(0xffffffffu, s1, o);
        s2 += __shfl_xor_sync(0xffffffffu, s2, o);
    }
    __shared__ float r1[8], r2[8];
    if ((t & 31) == 0) { r1[t >> 5] = s1; r2[t >> 5] = s2; }
    __syncthreads();
    float S1 = 0.f, S2 = 0.f;
#pragma unroll
    for (int i = 0; i < 8; ++i) { S1 += r1[i]; S2 += r2[i]; }
    float mean = S1 * (1.f / 256.f);
    float var  = S2 * (1.f / 256.f) - mean * mean;
    float o = (v - mean) * rsqrtf(var + 1e-5f) * gamma[t] + beta[t];
    outtf[m * 256 + t] = f2tf(o);
}

// ---------------------------------------------------------------------------
extern "C" void kernel_launch(void* const* d_in, const int* in_sizes, int n_in,
                              void* d_out, int out_size)
{
    (void)in_sizes; (void)n_in; (void)out_size;
    const float* x    = (const float*)d_in[0];
    const float* Wih0 = (const float*)d_in[1];
    const float* Whh0 = (const float*)d_in[2];
    const float* bih0 = (const float*)d_in[3];
    const float* bhh0 = (const float*)d_in[4];
    const float* Wih1 = (const float*)d_in[5];
    const float* Whh1 = (const float*)d_in[6];
    const float* bih1 = (const float*)d_in[7];
    const float* bhh1 = (const float*)d_in[8];
    const float* lng  = (const float*)d_in[9];
    const float* lnb  = (const float*)d_in[10];
    const float* cw1  = (const float*)d_in[11];
    const float* cb1  = (const float*)d_in[12];
    const float* cw2  = (const float*)d_in[13];
    const float* cb2  = (const float*)d_in[14];
    const float* sw1  = (const float*)d_in[15];
    const float* sb1  = (const float*)d_in[16];
    const float* sw2  = (const float*)d_in[17];
    const float* sb2  = (const float*)d_in[18];
    const float* lw1  = (const float*)d_in[19];
    const float* lb1  = (const float*)d_in[20];
    const float* lw2  = (const float*)d_in[21];
    const float* lb2  = (const float*)d_in[22];
    float* out = (float*)d_out;

    uint32_t *xbt, *h0tf, *h1tf, *httf, *Wre0, *Wre1, *Wh1;
    float *h1f, *c0, *c1, *hid, *bre0, *bre1, *bh1;
    cudaGetSymbolAddress((void**)&xbt,  g_xbt);
    cudaGetSymbolAddress((void**)&h0tf, g_h0tf);
    cudaGetSymbolAddress((void**)&h1tf, g_h1tf);
    cudaGetSymbolAddress((void**)&httf, g_httf);
    cudaGetSymbolAddress((void**)&h1f,  g_h1f);
    cudaGetSymbolAddress((void**)&c0,   g_c0);
    cudaGetSymbolAddress((void**)&c1,   g_c1);
    cudaGetSymbolAddress((void**)&hid,  g_hid);
    cudaGetSymbolAddress((void**)&Wre0, g_Wre0);
    cudaGetSymbolAddress((void**)&Wre1, g_Wre1);
    cudaGetSymbolAddress((void**)&bre0, g_bre0);
    cudaGetSymbolAddress((void**)&bre1, g_bre1);
    cudaGetSymbolAddress((void**)&Wh1,  g_Wh1);
    cudaGetSymbolAddress((void**)&bh1,  g_bh1);

    uint32_t* H0[2] = {h0tf, h0tf + BNR * HD};
    uint32_t* H1[2] = {h1tf, h1tf + BNR * HD};

    transpose_kernel<<<25600, 256>>>(x);
    rearr_w_kernel<<<2048, 256>>>(Wih0, Whh0, bih0, bhh0, Wre0, bre0);
    rearr_w_kernel<<<2048, 256>>>(Wih1, Whh1, bih1, bhh1, Wre1, bre1);
    rearr_h1_kernel<<<512, 256>>>(cw1, cb1, sw1, sb1, lw1, lb1);
    zero_state_kernel<<<1600, 256>>>();

    dim3 cg(13, 32);
    int p0 = 0, p1 = 0;
    for (int t = 0; t < SEQ; ++t) {
        cell_kernel<<<cg, 256>>>(xbt + t * HD, SEQ * HD,
                                 H0[p0], HD, Wre0, bre0,
                                 c0, nullptr, H0[p0 ^ 1]);
        cell_kernel<<<cg, 256>>>(H0[p0 ^ 1], HD,
                                 H1[p1], HD, Wre1, bre1,
                                 c1, h1f, H1[p1 ^ 1]);
        p0 ^= 1; p1 ^= 1;
    }
    ln_kernel<<<1600, 256>>>(h1f, lng, lnb, httf);

    for (int s = 0; s < NSTEPS; ++s) {
        heads1_kernel<<<dim3(13, 16), 256>>>(httf, Wh1, bh1, hid);
        heads2_kernel<<<1600, 128>>>(hid, cw2, cb2, sw2, sb2, lw2, lb2, out, s);
        if (s < NSTEPS - 1) {
            cell_kernel<<<cg, 256>>>(httf, HD,
                                     H0[p0], HD, Wre0, bre0,
                                     c0, nullptr, H0[p0 ^ 1]);
            cell_kernel<<<cg, 256>>>(H0[p0 ^ 1], HD,
                                     H1[p1], HD, Wre1, bre1,
                                     c1, h1f, H1[p1 ^ 1]);
            p0 ^= 1; p1 ^= 1;
            ln_kernel<<<1600, 256>>>(h1f, lng, lnb, httf);
        }
    }
}